// round 1
// baseline (speedup 1.0000x reference)
#include <cuda_runtime.h>
#include <cuda_bf16.h>
#include <cstdint>
#include <cstddef>

// ---------------------------------------------------------------------------
// Problem constants (match reference)
// ---------------------------------------------------------------------------
constexpr int N_SRC1 = 200000;
constexpr int N_TGT1 = 50000;
constexpr int N_TGT2 = 10000;
constexpr int E1C    = 1000000;
constexpr int E2C    = 300000;
constexpr int F_IN   = 256;
constexpr int F_HID  = 192;
constexpr int F_OUT  = 128;

// ---------------------------------------------------------------------------
// Scratch (static device globals: allocation-free per harness rules)
// ---------------------------------------------------------------------------
__device__ float g_agg1[(size_t)N_TGT1 * F_IN];    // 51.2 MB
__device__ float g_cnt1[N_TGT1];
__device__ float g_h1[(size_t)N_TGT1 * F_HID];     // 38.4 MB
__device__ float g_agg2[(size_t)N_TGT2 * F_HID];   // 7.7 MB
__device__ float g_cnt2[N_TGT2];
__device__ float g_h2[(size_t)N_TGT2 * F_HID];     // 7.7 MB

// ---------------------------------------------------------------------------
// Reduction helpers: vector red.global (4x fewer atomic instructions)
// ---------------------------------------------------------------------------
__device__ __forceinline__ void red_add4(float* p, float4 v) {
    asm volatile("red.global.add.v4.f32 [%0], {%1, %2, %3, %4};"
                 :: "l"(p), "f"(v.x), "f"(v.y), "f"(v.z), "f"(v.w) : "memory");
}
__device__ __forceinline__ void red_add1(float* p, float v) {
    asm volatile("red.global.add.f32 [%0], %1;" :: "l"(p), "f"(v) : "memory");
}

// ---------------------------------------------------------------------------
// Zero the accumulators (must run before each scatter pass)
// ---------------------------------------------------------------------------
__global__ void __launch_bounds__(256) zero_kernel(float4* agg1, float* cnt1,
                                                   float4* agg2, float* cnt2) {
    int i = blockIdx.x * 256 + threadIdx.x;
    int st = gridDim.x * 256;
    const float4 z = make_float4(0.f, 0.f, 0.f, 0.f);
    for (int k = i; k < N_TGT1 * (F_IN / 4); k += st) agg1[k] = z;
    for (int k = i; k < N_TGT2 * (F_HID / 4); k += st) agg2[k] = z;
    for (int k = i; k < N_TGT1; k += st) cnt1[k] = 0.f;
    for (int k = i; k < N_TGT2; k += st) cnt2[k] = 0.f;
}

// ---------------------------------------------------------------------------
// Scatter 1: one warp per edge, 256 floats (64 float4) per edge
// ---------------------------------------------------------------------------
__global__ void __launch_bounds__(256) scatter1_kernel(const float* __restrict__ x,
                                                       const int* __restrict__ ei,
                                                       float* __restrict__ agg1,
                                                       float* __restrict__ cnt1) {
    int gw = (blockIdx.x * 256 + threadIdx.x) >> 5;
    int lane = threadIdx.x & 31;
    if (gw >= E1C) return;
    int src = __ldg(ei + gw);
    int tgt = __ldg(ei + E1C + gw);
    const float4* xr = (const float4*)(x + (size_t)src * F_IN);
    float* ar = agg1 + (size_t)tgt * F_IN;
#pragma unroll
    for (int i = 0; i < 2; i++) {
        int f = lane + 32 * i;               // float4 index 0..63
        float4 v = __ldg(xr + f);
        red_add4(ar + f * 4, v);
    }
    if (lane == 0) red_add1(cnt1 + tgt, 1.0f);
}

// ---------------------------------------------------------------------------
// Scatter 2: one warp per edge, 192 floats (48 float4) per edge
// ---------------------------------------------------------------------------
__global__ void __launch_bounds__(256) scatter2_kernel(const float* __restrict__ h1,
                                                       const int* __restrict__ ei,
                                                       float* __restrict__ agg2,
                                                       float* __restrict__ cnt2) {
    int gw = (blockIdx.x * 256 + threadIdx.x) >> 5;
    int lane = threadIdx.x & 31;
    if (gw >= E2C) return;
    int src = __ldg(ei + gw);
    int tgt = __ldg(ei + E2C + gw);
    const float4* hr = (const float4*)(h1 + (size_t)src * F_HID);
    float* ar = agg2 + (size_t)tgt * F_HID;
#pragma unroll
    for (int i = 0; i < 2; i++) {
        int f = lane + 32 * i;               // float4 index 0..47
        if (f < F_HID / 4) {
            float4 v = __ldg(hr + f);
            red_add4(ar + f * 4, v);
        }
    }
    if (lane == 0) red_add1(cnt2 + tgt, 1.0f);
}

// ---------------------------------------------------------------------------
// Generic fused GEMM:
//   C[M,192] = act( (A1/max(cnt,1)) @ B1^T + A2 @ B2^T + bias )
// A1:[M,K1] pitch K1, A2:[M,K2] pitch K2, B1:[192,K1], B2:[192,K2].
// Block tile 64x192, threads (16,16), micro-tile 4 rows x 12 cols.
// ---------------------------------------------------------------------------
template<int K1, int K2, bool MEAN, bool RELU>
__global__ void __launch_bounds__(256) gemm_fused(
    const float* __restrict__ A1, const float* __restrict__ cnt,
    const float* __restrict__ A2,
    const float* __restrict__ B1, const float* __restrict__ B2,
    const float* __restrict__ bias, float* __restrict__ C, int M)
{
    constexpr int BM = 64, BK = 16, NC = 192;
    __shared__ float As[BK][68];      // [kk][row], pitch 68 (272B, 16B-mult)
    __shared__ float Bs[BK][196];     // [kk][col], pitch 196 (784B, 16B-mult)
    __shared__ float inv_s[BM];

    const int tx = threadIdx.x;       // 0..15 -> 12 cols each
    const int ty = threadIdx.y;       // 0..15 -> 4 rows each
    const int t  = ty * 16 + tx;
    const int row0 = blockIdx.x * BM;

    if (t < BM) {
        float iv = 1.0f;
        if (MEAN) {
            int r = row0 + t;
            float c = (r < M) ? cnt[r] : 1.0f;
            iv = 1.0f / fmaxf(c, 1.0f);
        }
        inv_s[t] = iv;
    }
    __syncthreads();

    float acc[4][12];
#pragma unroll
    for (int r = 0; r < 4; r++)
#pragma unroll
        for (int c = 0; c < 12; c++) acc[r][c] = 0.f;

    const int lr = t >> 2;            // 0..63 (row for A load / col-base for B)
    const int kq = (t & 3) * 4;       // 0,4,8,12

    // ---- phase 1: A1 (optionally mean-scaled) vs B1 ----
    for (int k0 = 0; k0 < K1; k0 += BK) {
        {
            int row = row0 + lr;
            float4 v = make_float4(0.f, 0.f, 0.f, 0.f);
            if (row < M) v = *(const float4*)(A1 + (size_t)row * K1 + k0 + kq);
            if (MEAN) {
                float iv = inv_s[lr];
                v.x *= iv; v.y *= iv; v.z *= iv; v.w *= iv;
            }
            As[kq + 0][lr] = v.x; As[kq + 1][lr] = v.y;
            As[kq + 2][lr] = v.z; As[kq + 3][lr] = v.w;
        }
#pragma unroll
        for (int j = 0; j < 3; j++) {
            int n = lr + 64 * j;
            float4 w = *(const float4*)(B1 + (size_t)n * K1 + k0 + kq);
            Bs[kq + 0][n] = w.x; Bs[kq + 1][n] = w.y;
            Bs[kq + 2][n] = w.z; Bs[kq + 3][n] = w.w;
        }
        __syncthreads();
#pragma unroll
        for (int kk = 0; kk < BK; kk++) {
            float4 a = *(const float4*)&As[kk][ty * 4];
            float b[12];
#pragma unroll
            for (int c3 = 0; c3 < 3; c3++) {
                float4 bb = *(const float4*)&Bs[kk][tx * 12 + c3 * 4];
                b[c3 * 4 + 0] = bb.x; b[c3 * 4 + 1] = bb.y;
                b[c3 * 4 + 2] = bb.z; b[c3 * 4 + 3] = bb.w;
            }
            float av[4] = {a.x, a.y, a.z, a.w};
#pragma unroll
            for (int r = 0; r < 4; r++)
#pragma unroll
                for (int c = 0; c < 12; c++) acc[r][c] += av[r] * b[c];
        }
        __syncthreads();
    }

    // ---- phase 2: A2 vs B2 (no scaling) ----
    if constexpr (K2 > 0) {
        for (int k0 = 0; k0 < K2; k0 += BK) {
            {
                int row = row0 + lr;
                float4 v = make_float4(0.f, 0.f, 0.f, 0.f);
                if (row < M) v = *(const float4*)(A2 + (size_t)row * K2 + k0 + kq);
                As[kq + 0][lr] = v.x; As[kq + 1][lr] = v.y;
                As[kq + 2][lr] = v.z; As[kq + 3][lr] = v.w;
            }
#pragma unroll
            for (int j = 0; j < 3; j++) {
                int n = lr + 64 * j;
                float4 w = *(const float4*)(B2 + (size_t)n * K2 + k0 + kq);
                Bs[kq + 0][n] = w.x; Bs[kq + 1][n] = w.y;
                Bs[kq + 2][n] = w.z; Bs[kq + 3][n] = w.w;
            }
            __syncthreads();
#pragma unroll
            for (int kk = 0; kk < BK; kk++) {
                float4 a = *(const float4*)&As[kk][ty * 4];
                float b[12];
#pragma unroll
                for (int c3 = 0; c3 < 3; c3++) {
                    float4 bb = *(const float4*)&Bs[kk][tx * 12 + c3 * 4];
                    b[c3 * 4 + 0] = bb.x; b[c3 * 4 + 1] = bb.y;
                    b[c3 * 4 + 2] = bb.z; b[c3 * 4 + 3] = bb.w;
                }
                float av[4] = {a.x, a.y, a.z, a.w};
#pragma unroll
                for (int r = 0; r < 4; r++)
#pragma unroll
                    for (int c = 0; c < 12; c++) acc[r][c] += av[r] * b[c];
            }
            __syncthreads();
        }
    }

    // ---- epilogue: bias (+ReLU), store ----
#pragma unroll
    for (int c = 0; c < 12; c++) {
        int col = tx * 12 + c;
        float bv = __ldg(bias + col);
#pragma unroll
        for (int r = 0; r < 4; r++) {
            int row = row0 + ty * 4 + r;
            if (row < M) {
                float v = acc[r][c] + bv;
                if (RELU) v = fmaxf(v, 0.f);
                C[(size_t)row * NC + col] = v;
            }
        }
    }
}

// ---------------------------------------------------------------------------
// Final: logits = relu(emb) @ W2^T + b2, then log_softmax per row.
// One block = 8 rows, 128 threads (one per output col). W2 transposed in smem.
// Dynamic smem: wT[192*128] + hs[8*192] + red[8]
// ---------------------------------------------------------------------------
__global__ void __launch_bounds__(128) mlp_out_kernel(const float* __restrict__ emb,
                                                      const float* __restrict__ W2,
                                                      const float* __restrict__ b2,
                                                      float* __restrict__ out) {
    constexpr int R = 8;
    extern __shared__ float sm[];
    float* wT  = sm;                       // [192][128]
    float* hs  = wT + 192 * 128;           // [R][192]
    float* red = hs + R * 192;             // [R]

    const int t = threadIdx.x;             // 0..127
    const int row0 = blockIdx.x * R;

    // Load + transpose W2: thread t owns W2 row t (128 rows x 192 cols).
#pragma unroll 4
    for (int f = 0; f < F_HID / 4; f++) {
        float4 v = *(const float4*)(W2 + (size_t)t * F_HID + f * 4);
        wT[(f * 4 + 0) * 128 + t] = v.x;
        wT[(f * 4 + 1) * 128 + t] = v.y;
        wT[(f * 4 + 2) * 128 + t] = v.z;
        wT[(f * 4 + 3) * 128 + t] = v.w;
    }
    // Load embedding rows with ReLU applied.
    for (int i = t; i < R * (F_HID / 4); i += 128) {
        float4 v = ((const float4*)(emb + (size_t)row0 * F_HID))[i];
        v.x = fmaxf(v.x, 0.f); v.y = fmaxf(v.y, 0.f);
        v.z = fmaxf(v.z, 0.f); v.w = fmaxf(v.w, 0.f);
        ((float4*)hs)[i] = v;
    }
    __syncthreads();

    float acc[R];
    float bb = __ldg(b2 + t);
#pragma unroll
    for (int r = 0; r < R; r++) acc[r] = bb;

    for (int k = 0; k < F_HID; k += 4) {
        float w0 = wT[(k + 0) * 128 + t];
        float w1 = wT[(k + 1) * 128 + t];
        float w2 = wT[(k + 2) * 128 + t];
        float w3 = wT[(k + 3) * 128 + t];
#pragma unroll
        for (int r = 0; r < R; r++) {
            float4 h = *(const float4*)&hs[r * F_HID + k];
            acc[r] += w0 * h.x + w1 * h.y + w2 * h.z + w3 * h.w;
        }
    }
    __syncthreads();   // done reading wT; reuse its space for logits

    float* lg = wT;    // [R][128]
#pragma unroll
    for (int r = 0; r < R; r++) lg[r * 128 + t] = acc[r];
    __syncthreads();

    int wp = t >> 5, lane = t & 31;
#pragma unroll
    for (int rr = 0; rr < 2; rr++) {
        int r = wp * 2 + rr;
        float v0 = lg[r * 128 + lane];
        float v1 = lg[r * 128 + lane + 32];
        float v2 = lg[r * 128 + lane + 64];
        float v3 = lg[r * 128 + lane + 96];
        float m = fmaxf(fmaxf(v0, v1), fmaxf(v2, v3));
#pragma unroll
        for (int o = 16; o; o >>= 1) m = fmaxf(m, __shfl_xor_sync(0xffffffffu, m, o));
        float s = expf(v0 - m) + expf(v1 - m) + expf(v2 - m) + expf(v3 - m);
#pragma unroll
        for (int o = 16; o; o >>= 1) s += __shfl_xor_sync(0xffffffffu, s, o);
        if (lane == 0) red[r] = m + logf(s);
    }
    __syncthreads();

#pragma unroll
    for (int r = 0; r < R; r++)
        out[(size_t)(row0 + r) * F_OUT + t] = acc[r] - red[r];
}

// ---------------------------------------------------------------------------
// Launch
// ---------------------------------------------------------------------------
extern "C" void kernel_launch(void* const* d_in, const int* in_sizes, int n_in,
                              void* d_out, int out_size) {
    const float* x   = (const float*)d_in[0];
    const int*   ei1 = (const int*)d_in[1];
    const int*   ei2 = (const int*)d_in[2];
    const float* Wl1 = (const float*)d_in[3];
    const float* bl1 = (const float*)d_in[4];
    const float* Wr1 = (const float*)d_in[5];
    const float* Wl2 = (const float*)d_in[6];
    const float* bl2 = (const float*)d_in[7];
    const float* Wr2 = (const float*)d_in[8];
    const float* W1  = (const float*)d_in[9];
    const float* b1  = (const float*)d_in[10];
    const float* W2  = (const float*)d_in[11];
    const float* b2  = (const float*)d_in[12];

    float* out  = (float*)d_out;
    float* logp = out;                                   // [10000,128]
    float* emb  = out + (size_t)N_TGT2 * F_OUT;          // [10000,192]

    float *agg1, *cnt1, *h1, *agg2, *cnt2, *h2;
    cudaGetSymbolAddress((void**)&agg1, g_agg1);
    cudaGetSymbolAddress((void**)&cnt1, g_cnt1);
    cudaGetSymbolAddress((void**)&h1,   g_h1);
    cudaGetSymbolAddress((void**)&agg2, g_agg2);
    cudaGetSymbolAddress((void**)&cnt2, g_cnt2);
    cudaGetSymbolAddress((void**)&h2,   g_h2);

    // 1) zero accumulators
    zero_kernel<<<2048, 256>>>((float4*)agg1, cnt1, (float4*)agg2, cnt2);

    // 2) layer-1 scatter (mean numerator + counts)
    scatter1_kernel<<<E1C / 8, 256>>>(x, ei1, agg1, cnt1);

    // 3) layer-1 SAGE: h1 = relu(mean(agg1) @ Wl1^T + bl1 + x @ Wr1^T)
    gemm_fused<F_IN, F_IN, true, true>
        <<<(N_TGT1 + 63) / 64, dim3(16, 16)>>>(agg1, cnt1, x, Wl1, Wr1, bl1, h1, N_TGT1);

    // 4) layer-2 scatter
    scatter2_kernel<<<(E2C * 32) / 256, 256>>>(h1, ei2, agg2, cnt2);

    // 5) layer-2 SAGE: h2 = relu(mean(agg2) @ Wl2^T + bl2 + h1 @ Wr2^T)
    gemm_fused<F_HID, F_HID, true, true>
        <<<(N_TGT2 + 63) / 64, dim3(16, 16)>>>(agg2, cnt2, h1, Wl2, Wr2, bl2, h2, N_TGT2);

    // 6) embedding = h2 @ W1^T + b1 (no relu; written straight to output)
    gemm_fused<F_HID, 0, false, false>
        <<<(N_TGT2 + 63) / 64, dim3(16, 16)>>>(h2, nullptr, nullptr, W1, nullptr, b1, emb, N_TGT2);

    // 7) logits + log_softmax (ReLU applied on load of emb)
    constexpr int MLP_SMEM = (192 * 128 + 8 * 192 + 8) * (int)sizeof(float);
    cudaFuncSetAttribute(mlp_out_kernel, cudaFuncAttributeMaxDynamicSharedMemorySize, MLP_SMEM);
    mlp_out_kernel<<<N_TGT2 / 8, 128, MLP_SMEM>>>(emb, W2, b2, logp);
}

// round 2
// speedup vs baseline: 1.1260x; 1.1260x over previous
#include <cuda_runtime.h>
#include <cuda_bf16.h>
#include <cstdint>
#include <cstddef>

// ---------------------------------------------------------------------------
// Problem constants
// ---------------------------------------------------------------------------
constexpr int N_SRC1 = 200000;
constexpr int N_TGT1 = 50000;
constexpr int N_TGT2 = 10000;
constexpr int E1C    = 1000000;
constexpr int E2C    = 300000;
constexpr int F_IN   = 256;
constexpr int F_HID  = 192;
constexpr int F_OUT  = 128;

// ---------------------------------------------------------------------------
// Scratch (static device globals)
// ---------------------------------------------------------------------------
__device__ float g_agg1[(size_t)N_TGT1 * F_IN];    // mean-aggregated features, layer 1
__device__ float g_h1[(size_t)N_TGT1 * F_HID];
__device__ float g_agg2[(size_t)N_TGT2 * F_HID];
__device__ float g_h2[(size_t)N_TGT2 * F_HID];

__device__ int g_cnt1[N_TGT1];
__device__ int g_cnt2[N_TGT2];
__device__ int g_start1[N_TGT1 + 1];
__device__ int g_start2[N_TGT2 + 1];
__device__ int g_cur1[N_TGT1];
__device__ int g_cur2[N_TGT2];
__device__ int g_srcs1[E1C];
__device__ int g_srcs2[E2C];

// ---------------------------------------------------------------------------
// f32x2 packed-FMA helpers (sm_100+: ptxas never emits FFMA2 from C++)
// ---------------------------------------------------------------------------
__device__ __forceinline__ void fma2(unsigned long long& d,
                                     unsigned long long a, unsigned long long b) {
    asm("fma.rn.f32x2 %0, %1, %2, %0;" : "+l"(d) : "l"(a), "l"(b));
}
__device__ __forceinline__ unsigned long long pack2(float x, float y) {
    unsigned long long r;
    asm("mov.b64 %0, {%1, %2};" : "=l"(r) : "f"(x), "f"(y));
    return r;
}
__device__ __forceinline__ void unpack2(unsigned long long v, float& lo, float& hi) {
    asm("mov.b64 {%0, %1}, %2;" : "=f"(lo), "=f"(hi) : "l"(v));
}

__device__ __forceinline__ float4 f4add(float4 a, float4 b) {
    return make_float4(a.x + b.x, a.y + b.y, a.z + b.z, a.w + b.w);
}

// ---------------------------------------------------------------------------
// CSR build: zero counts -> histogram -> scan -> fill
// ---------------------------------------------------------------------------
__global__ void __launch_bounds__(256) zero_counts_kernel(int* c1, int* c2) {
    int i = blockIdx.x * 256 + threadIdx.x;
    if (i < N_TGT1) c1[i] = 0;
    if (i < N_TGT2) c2[i] = 0;
}

__global__ void __launch_bounds__(256) hist_kernel(const int* __restrict__ ei1,
                                                   const int* __restrict__ ei2,
                                                   int* c1, int* c2) {
    int i = blockIdx.x * 256 + threadIdx.x;
    if (i < E1C) atomicAdd(c1 + __ldg(ei1 + E1C + i), 1);
    if (i < E2C) atomicAdd(c2 + __ldg(ei2 + E2C + i), 1);
}

// Two blocks: block 0 scans counts1 -> start1/cur1, block 1 scans counts2.
__global__ void __launch_bounds__(1024) scan2_kernel(const int* c1, int* s1, int* cur1,
                                                     const int* c2, int* s2, int* cur2) {
    __shared__ int sm[1024];
    int t = threadIdx.x;
    const int* c; int* s; int* cur; int n;
    if (blockIdx.x == 0) { c = c1; s = s1; cur = cur1; n = N_TGT1; }
    else                 { c = c2; s = s2; cur = cur2; n = N_TGT2; }
    int chunk = (n + 1023) >> 10;
    int base = t * chunk;
    int sum = 0;
    for (int i = 0; i < chunk; i++) {
        int idx = base + i;
        if (idx < n) sum += c[idx];
    }
    sm[t] = sum;
    __syncthreads();
    int mine = sum;
    for (int d = 1; d < 1024; d <<= 1) {
        int v = (t >= d) ? sm[t - d] : 0;
        __syncthreads();
        sm[t] += v;
        __syncthreads();
    }
    int run = sm[t] - mine;   // exclusive prefix
    for (int i = 0; i < chunk; i++) {
        int idx = base + i;
        if (idx < n) { s[idx] = run; cur[idx] = run; run += c[idx]; }
    }
    if (t == 1023) s[n] = run;
}

__global__ void __launch_bounds__(256) fill_kernel(const int* __restrict__ ei1,
                                                   const int* __restrict__ ei2,
                                                   int* cur1, int* srcs1,
                                                   int* cur2, int* srcs2) {
    int i = blockIdx.x * 256 + threadIdx.x;
    if (i < E1C) {
        int t = __ldg(ei1 + E1C + i);
        int p = atomicAdd(cur1 + t, 1);
        srcs1[p] = __ldg(ei1 + i);
    }
    if (i < E2C) {
        int t = __ldg(ei2 + E2C + i);
        int p = atomicAdd(cur2 + t, 1);
        srcs2[p] = __ldg(ei2 + i);
    }
}

// ---------------------------------------------------------------------------
// Gather 1: warp per target, 256 floats (64 float4). Writes MEAN directly.
// ---------------------------------------------------------------------------
__global__ void __launch_bounds__(256) gather1_kernel(const float* __restrict__ x,
                                                      const int* __restrict__ srcs,
                                                      const int* __restrict__ start,
                                                      float* __restrict__ agg) {
    int gw = (blockIdx.x * 256 + threadIdx.x) >> 5;
    int lane = threadIdx.x & 31;
    if (gw >= N_TGT1) return;
    int s = start[gw], e = start[gw + 1];
    float4 a0 = make_float4(0.f, 0.f, 0.f, 0.f);
    float4 a1 = make_float4(0.f, 0.f, 0.f, 0.f);
    for (int base = s; base < e; base += 32) {
        int m = e - base; if (m > 32) m = 32;
        int idx = (lane < m) ? __ldg(srcs + base + lane) : 0;
        int j = 0;
        for (; j + 2 <= m; j += 2) {
            int s0 = __shfl_sync(0xffffffffu, idx, j);
            int s1 = __shfl_sync(0xffffffffu, idx, j + 1);
            const float4* r0 = (const float4*)(x + (size_t)s0 * F_IN);
            const float4* r1 = (const float4*)(x + (size_t)s1 * F_IN);
            float4 v00 = __ldg(r0 + lane), v01 = __ldg(r0 + lane + 32);
            float4 v10 = __ldg(r1 + lane), v11 = __ldg(r1 + lane + 32);
            a0 = f4add(a0, f4add(v00, v10));
            a1 = f4add(a1, f4add(v01, v11));
        }
        if (j < m) {
            int s0 = __shfl_sync(0xffffffffu, idx, j);
            const float4* r0 = (const float4*)(x + (size_t)s0 * F_IN);
            a0 = f4add(a0, __ldg(r0 + lane));
            a1 = f4add(a1, __ldg(r0 + lane + 32));
        }
    }
    float inv = 1.0f / fmaxf((float)(e - s), 1.0f);
    float4* ar = (float4*)(agg + (size_t)gw * F_IN);
    ar[lane]      = make_float4(a0.x * inv, a0.y * inv, a0.z * inv, a0.w * inv);
    ar[lane + 32] = make_float4(a1.x * inv, a1.y * inv, a1.z * inv, a1.w * inv);
}

// ---------------------------------------------------------------------------
// Gather 2: warp per target, 192 floats (48 float4). Writes MEAN directly.
// ---------------------------------------------------------------------------
__global__ void __launch_bounds__(256) gather2_kernel(const float* __restrict__ h1,
                                                      const int* __restrict__ srcs,
                                                      const int* __restrict__ start,
                                                      float* __restrict__ agg) {
    int gw = (blockIdx.x * 256 + threadIdx.x) >> 5;
    int lane = threadIdx.x & 31;
    if (gw >= N_TGT2) return;
    int s = start[gw], e = start[gw + 1];
    float4 a0 = make_float4(0.f, 0.f, 0.f, 0.f);
    float4 a1 = make_float4(0.f, 0.f, 0.f, 0.f);
    bool hi = (lane < 16);    // float4 index 32 + lane valid only for lane < 16
    for (int base = s; base < e; base += 32) {
        int m = e - base; if (m > 32) m = 32;
        int idx = (lane < m) ? __ldg(srcs + base + lane) : 0;
        for (int j = 0; j < m; j++) {
            int s0 = __shfl_sync(0xffffffffu, idx, j);
            const float4* r0 = (const float4*)(h1 + (size_t)s0 * F_HID);
            a0 = f4add(a0, __ldg(r0 + lane));
            if (hi) a1 = f4add(a1, __ldg(r0 + lane + 32));
        }
    }
    float inv = 1.0f / fmaxf((float)(e - s), 1.0f);
    float4* ar = (float4*)(agg + (size_t)gw * F_HID);
    ar[lane] = make_float4(a0.x * inv, a0.y * inv, a0.z * inv, a0.w * inv);
    if (hi)
        ar[lane + 32] = make_float4(a1.x * inv, a1.y * inv, a1.z * inv, a1.w * inv);
}

// ---------------------------------------------------------------------------
// Fused GEMM: C[M,192] = act( A1 @ B1^T + A2 @ B2^T + bias )
// Block tile 64x192, threads (16,16), micro-tile 4 rows x 12 cols.
// Inner product uses packed fma.rn.f32x2 (2 fp32 FMA per instruction).
// ---------------------------------------------------------------------------
__device__ __forceinline__ void mma_tile16(const float (*As)[68], const float (*Bs)[196],
                                           int ty, int tx,
                                           unsigned long long (&acc)[4][6]) {
#pragma unroll
    for (int kk = 0; kk < 16; kk++) {
        float4 a = *(const float4*)&As[kk][ty * 4];
        unsigned long long a2[4];
        a2[0] = pack2(a.x, a.x); a2[1] = pack2(a.y, a.y);
        a2[2] = pack2(a.z, a.z); a2[3] = pack2(a.w, a.w);
        const unsigned long long* bp = (const unsigned long long*)&Bs[kk][tx * 12];
#pragma unroll
        for (int c = 0; c < 6; c++) {
            unsigned long long b2 = bp[c];
#pragma unroll
            for (int r = 0; r < 4; r++) fma2(acc[r][c], a2[r], b2);
        }
    }
}

template<int K1, int K2, bool RELU>
__global__ void __launch_bounds__(256) gemm_fused(
    const float* __restrict__ A1, const float* __restrict__ A2,
    const float* __restrict__ B1, const float* __restrict__ B2,
    const float* __restrict__ bias, float* __restrict__ C, int M)
{
    constexpr int BM = 64, BK = 16, NC = 192;
    __shared__ float As[BK][68];
    __shared__ float Bs[BK][196];

    const int tx = threadIdx.x;       // 0..15 -> 12 cols each
    const int ty = threadIdx.y;       // 0..15 -> 4 rows each
    const int t  = ty * 16 + tx;
    const int row0 = blockIdx.x * BM;

    unsigned long long acc[4][6];
#pragma unroll
    for (int r = 0; r < 4; r++)
#pragma unroll
        for (int c = 0; c < 6; c++) acc[r][c] = 0ull;

    const int lr = t >> 2;            // 0..63
    const int kq = (t & 3) * 4;       // 0,4,8,12

    // ---- phase 1: A1 vs B1 ----
    for (int k0 = 0; k0 < K1; k0 += BK) {
        {
            int row = row0 + lr;
            float4 v = make_float4(0.f, 0.f, 0.f, 0.f);
            if (row < M) v = *(const float4*)(A1 + (size_t)row * K1 + k0 + kq);
            As[kq + 0][lr] = v.x; As[kq + 1][lr] = v.y;
            As[kq + 2][lr] = v.z; As[kq + 3][lr] = v.w;
        }
#pragma unroll
        for (int j = 0; j < 3; j++) {
            int n = lr + 64 * j;
            float4 w = *(const float4*)(B1 + (size_t)n * K1 + k0 + kq);
            Bs[kq + 0][n] = w.x; Bs[kq + 1][n] = w.y;
            Bs[kq + 2][n] = w.z; Bs[kq + 3][n] = w.w;
        }
        __syncthreads();
        mma_tile16(As, Bs, ty, tx, acc);
        __syncthreads();
    }

    // ---- phase 2: A2 vs B2 ----
    if constexpr (K2 > 0) {
        for (int k0 = 0; k0 < K2; k0 += BK) {
            {
                int row = row0 + lr;
                float4 v = make_float4(0.f, 0.f, 0.f, 0.f);
                if (row < M) v = *(const float4*)(A2 + (size_t)row * K2 + k0 + kq);
                As[kq + 0][lr] = v.x; As[kq + 1][lr] = v.y;
                As[kq + 2][lr] = v.z; As[kq + 3][lr] = v.w;
            }
#pragma unroll
            for (int j = 0; j < 3; j++) {
                int n = lr + 64 * j;
                float4 w = *(const float4*)(B2 + (size_t)n * K2 + k0 + kq);
                Bs[kq + 0][n] = w.x; Bs[kq + 1][n] = w.y;
                Bs[kq + 2][n] = w.z; Bs[kq + 3][n] = w.w;
            }
            __syncthreads();
            mma_tile16(As, Bs, ty, tx, acc);
            __syncthreads();
        }
    }

    // ---- epilogue ----
#pragma unroll
    for (int c = 0; c < 6; c++) {
        int col = tx * 12 + c * 2;
        float b0 = __ldg(bias + col);
        float b1 = __ldg(bias + col + 1);
#pragma unroll
        for (int r = 0; r < 4; r++) {
            int row = row0 + ty * 4 + r;
            if (row < M) {
                float lo, hi;
                unpack2(acc[r][c], lo, hi);
                lo += b0; hi += b1;
                if (RELU) { lo = fmaxf(lo, 0.f); hi = fmaxf(hi, 0.f); }
                *(float2*)(C + (size_t)row * NC + col) = make_float2(lo, hi);
            }
        }
    }
}

// ---------------------------------------------------------------------------
// Final: logits = relu(emb) @ W2^T + b2, then log_softmax per row.
// ---------------------------------------------------------------------------
__global__ void __launch_bounds__(128) mlp_out_kernel(const float* __restrict__ emb,
                                                      const float* __restrict__ W2,
                                                      const float* __restrict__ b2,
                                                      float* __restrict__ out) {
    constexpr int R = 8;
    extern __shared__ float sm[];
    float* wT  = sm;                       // [192][128]
    float* hs  = wT + 192 * 128;           // [R][192]
    float* red = hs + R * 192;             // [R]

    const int t = threadIdx.x;             // 0..127
    const int row0 = blockIdx.x * R;

#pragma unroll 4
    for (int f = 0; f < F_HID / 4; f++) {
        float4 v = *(const float4*)(W2 + (size_t)t * F_HID + f * 4);
        wT[(f * 4 + 0) * 128 + t] = v.x;
        wT[(f * 4 + 1) * 128 + t] = v.y;
        wT[(f * 4 + 2) * 128 + t] = v.z;
        wT[(f * 4 + 3) * 128 + t] = v.w;
    }
    for (int i = t; i < R * (F_HID / 4); i += 128) {
        float4 v = ((const float4*)(emb + (size_t)row0 * F_HID))[i];
        v.x = fmaxf(v.x, 0.f); v.y = fmaxf(v.y, 0.f);
        v.z = fmaxf(v.z, 0.f); v.w = fmaxf(v.w, 0.f);
        ((float4*)hs)[i] = v;
    }
    __syncthreads();

    float acc[R];
    float bb = __ldg(b2 + t);
#pragma unroll
    for (int r = 0; r < R; r++) acc[r] = bb;

    for (int k = 0; k < F_HID; k += 4) {
        float w0 = wT[(k + 0) * 128 + t];
        float w1 = wT[(k + 1) * 128 + t];
        float w2 = wT[(k + 2) * 128 + t];
        float w3 = wT[(k + 3) * 128 + t];
#pragma unroll
        for (int r = 0; r < R; r++) {
            float4 h = *(const float4*)&hs[r * F_HID + k];
            acc[r] += w0 * h.x + w1 * h.y + w2 * h.z + w3 * h.w;
        }
    }
    __syncthreads();

    float* lg = wT;
#pragma unroll
    for (int r = 0; r < R; r++) lg[r * 128 + t] = acc[r];
    __syncthreads();

    int wp = t >> 5, lane = t & 31;
#pragma unroll
    for (int rr = 0; rr < 2; rr++) {
        int r = wp * 2 + rr;
        float v0 = lg[r * 128 + lane];
        float v1 = lg[r * 128 + lane + 32];
        float v2 = lg[r * 128 + lane + 64];
        float v3 = lg[r * 128 + lane + 96];
        float m = fmaxf(fmaxf(v0, v1), fmaxf(v2, v3));
#pragma unroll
        for (int o = 16; o; o >>= 1) m = fmaxf(m, __shfl_xor_sync(0xffffffffu, m, o));
        float s = expf(v0 - m) + expf(v1 - m) + expf(v2 - m) + expf(v3 - m);
#pragma unroll
        for (int o = 16; o; o >>= 1) s += __shfl_xor_sync(0xffffffffu, s, o);
        if (lane == 0) red[r] = m + logf(s);
    }
    __syncthreads();

#pragma unroll
    for (int r = 0; r < R; r++)
        out[(size_t)(row0 + r) * F_OUT + t] = acc[r] - red[r];
}

// ---------------------------------------------------------------------------
// Launch
// ---------------------------------------------------------------------------
extern "C" void kernel_launch(void* const* d_in, const int* in_sizes, int n_in,
                              void* d_out, int out_size) {
    const float* x   = (const float*)d_in[0];
    const int*   ei1 = (const int*)d_in[1];
    const int*   ei2 = (const int*)d_in[2];
    const float* Wl1 = (const float*)d_in[3];
    const float* bl1 = (const float*)d_in[4];
    const float* Wr1 = (const float*)d_in[5];
    const float* Wl2 = (const float*)d_in[6];
    const float* bl2 = (const float*)d_in[7];
    const float* Wr2 = (const float*)d_in[8];
    const float* W1  = (const float*)d_in[9];
    const float* b1  = (const float*)d_in[10];
    const float* W2  = (const float*)d_in[11];
    const float* b2  = (const float*)d_in[12];

    float* out  = (float*)d_out;
    float* logp = out;                                   // [10000,128]
    float* emb  = out + (size_t)N_TGT2 * F_OUT;          // [10000,192]

    float *agg1, *h1, *agg2, *h2;
    int *cnt1, *cnt2, *start1, *start2, *cur1, *cur2, *srcs1, *srcs2;
    cudaGetSymbolAddress((void**)&agg1,   g_agg1);
    cudaGetSymbolAddress((void**)&h1,     g_h1);
    cudaGetSymbolAddress((void**)&agg2,   g_agg2);
    cudaGetSymbolAddress((void**)&h2,     g_h2);
    cudaGetSymbolAddress((void**)&cnt1,   g_cnt1);
    cudaGetSymbolAddress((void**)&cnt2,   g_cnt2);
    cudaGetSymbolAddress((void**)&start1, g_start1);
    cudaGetSymbolAddress((void**)&start2, g_start2);
    cudaGetSymbolAddress((void**)&cur1,   g_cur1);
    cudaGetSymbolAddress((void**)&cur2,   g_cur2);
    cudaGetSymbolAddress((void**)&srcs1,  g_srcs1);
    cudaGetSymbolAddress((void**)&srcs2,  g_srcs2);

    // CSR build (both layers)
    zero_counts_kernel<<<(N_TGT1 + 255) / 256, 256>>>(cnt1, cnt2);
    hist_kernel<<<(E1C + 255) / 256, 256>>>(ei1, ei2, cnt1, cnt2);
    scan2_kernel<<<2, 1024>>>(cnt1, start1, cur1, cnt2, start2, cur2);
    fill_kernel<<<(E1C + 255) / 256, 256>>>(ei1, ei2, cur1, srcs1, cur2, srcs2);

    // Layer 1: gather mean, then h1 = relu(agg1 @ Wl1^T + x @ Wr1^T + bl1)
    gather1_kernel<<<(N_TGT1 * 32 + 255) / 256, 256>>>(x, srcs1, start1, agg1);
    gemm_fused<F_IN, F_IN, true>
        <<<(N_TGT1 + 63) / 64, dim3(16, 16)>>>(agg1, x, Wl1, Wr1, bl1, h1, N_TGT1);

    // Layer 2
    gather2_kernel<<<(N_TGT2 * 32 + 255) / 256, 256>>>(h1, srcs2, start2, agg2);
    gemm_fused<F_HID, F_HID, true>
        <<<(N_TGT2 + 63) / 64, dim3(16, 16)>>>(agg2, h1, Wl2, Wr2, bl2, h2, N_TGT2);

    // embedding = h2 @ W1^T + b1
    gemm_fused<F_HID, 0, false>
        <<<(N_TGT2 + 63) / 64, dim3(16, 16)>>>(h2, nullptr, W1, nullptr, b1, emb, N_TGT2);

    // logits + log_softmax
    constexpr int MLP_SMEM = (192 * 128 + 8 * 192 + 8) * (int)sizeof(float);
    cudaFuncSetAttribute(mlp_out_kernel, cudaFuncAttributeMaxDynamicSharedMemorySize, MLP_SMEM);
    mlp_out_kernel<<<N_TGT2 / 8, 128, MLP_SMEM>>>(emb, W2, b2, logp);
}